// round 15
// baseline (speedup 1.0000x reference)
#include <cuda_runtime.h>
#include <math.h>

#define BB   4
#define NN   4096
#define CC   64
#define KNN  16
#define NH   4
#define QW   4
#define CAP  64
#define FULL 0xffffffffu
#define NEGINF (-3.402823466e+38f)

// ---------------- device scratch (allocation-free) ----------------
__device__ int    g_idx[BB * NN * KNN];
__device__ float4 g_PP [BB * NN];            // packed pos (x,y,z,|p|^2)
__device__ float  g_V  [BB * NN * CC];       // x @ Wv^T + bv
__device__ float  g_KL [BB * NN * NH];
__device__ float  g_QM [BB * NN * NH];
__device__ float  g_WvT [CC * CC];
__device__ float  g_WpT [CC * CC];
__device__ float  g_WfcT[CC * CC];
__device__ float  g_Wkm [CC * NH];
__device__ float  g_Wqm [CC * NH];
__device__ float  g_Wpm [CC * NH];
__device__ float  g_PW1 [CC * 4];
__device__ float  g_CB  [NH];

// ---------------- prep1 ----------------
__global__ void prep1_kernel(const float* __restrict__ Wq, const float* __restrict__ bq,
                             const float* __restrict__ Wk, const float* __restrict__ bk,
                             const float* __restrict__ Wv,
                             const float* __restrict__ Wp1, const float* __restrict__ bp1,
                             const float* __restrict__ Wp2, const float* __restrict__ bp2,
                             const float* __restrict__ Wfc) {
    int tg = blockIdx.x * 256 + threadIdx.x;
    {
        int r = tg >> 6, c = tg & 63;
        g_WvT [c * CC + r] = Wv [tg];
        g_WpT [c * CC + r] = Wp2[tg];
        g_WfcT[c * CC + r] = Wfc[tg];
    }
    if (blockIdx.x == 0) {
        int t = threadIdx.x;
        int c = t >> 2, h = t & 3;
        float sk = 0.f, sq = 0.f, sp = 0.f;
#pragma unroll
        for (int d = 0; d < 16; d++) {
            sk += Wk [(h * 16 + d) * CC + c];
            sq += Wq [(h * 16 + d) * CC + c];
            sp += Wp2[(h * 16 + d) * CC + c];
        }
        g_Wkm[c * NH + h] = sk * (1.f / 16.f);
        g_Wqm[c * NH + h] = sq * (1.f / 16.f);
        g_Wpm[c * NH + h] = sp * (1.f / 16.f);
        if (t < CC) {
            g_PW1[t * 4 + 0] = Wp1[t * 3 + 0];
            g_PW1[t * 4 + 1] = Wp1[t * 3 + 1];
            g_PW1[t * 4 + 2] = Wp1[t * 3 + 2];
            g_PW1[t * 4 + 3] = bp1[t];
        }
        if (t < NH) {
            float s1 = 0.f, s2 = 0.f, s3 = 0.f;
            for (int d = 0; d < 16; d++) {
                s1 += bq [t * 16 + d];
                s2 += bk [t * 16 + d];
                s3 += bp2[t * 16 + d];
            }
            g_CB[t] = (s1 - s2 + s3) * (1.f / 16.f);
        }
    }
}

// ---------------- prep2 ----------------
__global__ __launch_bounds__(256) void prep2_kernel(const float* __restrict__ x,
                                                    const float* __restrict__ pos,
                                                    const float* __restrict__ bv) {
    __shared__ float xs[16 * CC];
    const int t = threadIdx.x;
    const int pbase = blockIdx.x * 16;

    ((float4*)xs)[t] = ((const float4*)(x + (size_t)pbase * CC))[t];
    __syncthreads();

    const int pt = t >> 4;
    const int jj = t & 15;
    const int p  = pbase + pt;
    const float* xr = xs + pt * CC;

    float a0 = bv[jj * 4 + 0], a1 = bv[jj * 4 + 1],
          a2 = bv[jj * 4 + 2], a3 = bv[jj * 4 + 3];
#pragma unroll 8
    for (int c = 0; c < CC; c++) {
        float xv = xr[c];
        float4 w = ((const float4*)(g_WvT + c * CC))[jj];
        a0 = fmaf(xv, w.x, a0); a1 = fmaf(xv, w.y, a1);
        a2 = fmaf(xv, w.z, a2); a3 = fmaf(xv, w.w, a3);
    }
    ((float4*)(g_V + (size_t)p * CC))[jj] = make_float4(a0, a1, a2, a3);

    if (jj < 4) {
        float s = 0.f;
#pragma unroll 8
        for (int c = 0; c < CC; c++) s = fmaf(xr[c], g_Wkm[c * 4 + jj], s);
        g_KL[(size_t)p * 4 + jj] = s;
    } else if (jj < 8) {
        int h = jj - 4;
        float s = 0.f;
#pragma unroll 8
        for (int c = 0; c < CC; c++) s = fmaf(xr[c], g_Wqm[c * 4 + h], s);
        g_QM[(size_t)p * 4 + h] = s;
    } else if (jj == 8) {
        float px = pos[(size_t)p * 3 + 0];
        float py = pos[(size_t)p * 3 + 1];
        float pz = pos[(size_t)p * 3 + 2];
        float nn = px * px; nn = fmaf(py, py, nn); nn = fmaf(pz, pz, nn);
        g_PP[p] = make_float4(px, py, pz, nn);
    }
}

// ---------------- kNN helpers ----------------
__device__ __forceinline__ float knn_dist(const float4 qp, const float4 c4) {
    float inner = qp.x * c4.x;
    inner = fmaf(qp.y, c4.y, inner);
    inner = fmaf(qp.z, c4.z, inner);
    return fmaf(2.0f, inner, (-qp.w) - c4.w);
}

__device__ __forceinline__ void warp_min16(float tv, int ti,
                                           float& mv, int& mI, int& ml) {
    mv = tv; mI = ti; ml = threadIdx.x & 31;
#pragma unroll
    for (int off = 1; off < 16; off <<= 1) {
        float ov = __shfl_xor_sync(FULL, mv, off);
        int   oi = __shfl_xor_sync(FULL, mI, off);
        int   ol = __shfl_xor_sync(FULL, ml, off);
        if (ov < mv || (ov == mv && oi > mI)) { mv = ov; mI = oi; ml = ol; }
    }
    mv = __shfl_sync(FULL, mv, 0);
    mI = __shfl_sync(FULL, mI, 0);
    ml = __shfl_sync(FULL, ml, 0);
}

__device__ void knn_exact(const float4* PPb, const float4 qp, int q) {
    const int lane = threadIdx.x & 31;
    float tv = NEGINF; int ti = 0x7fffffff - lane;
    float wv = NEGINF; int wm = 0x7fffffff;
    for (int mi0 = 0; mi0 < NN; mi0 += 32) {
        int mi = mi0 + lane;
        float d = knn_dist(qp, PPb[mi]);
        bool pred = (d > wv) || (d == wv && mi < wm);
        unsigned mask = __ballot_sync(FULL, pred);
        while (mask) {
            int src = __ffs(mask) - 1; mask &= mask - 1;
            float dc = __shfl_sync(FULL, d, src);
            int   mc = __shfl_sync(FULL, mi, src);
            float mv; int mI, ml;
            warp_min16(tv, ti, mv, mI, ml);
            if (dc > mv || (dc == mv && mc < mI)) {
                if (lane == ml) { tv = dc; ti = mc; }
                warp_min16(tv, ti, mv, mI, ml);
            }
            wv = mv; wm = mI;
        }
    }
    if (lane < KNN) g_idx[(size_t)q * KNN + lane] = ti;
}

__device__ __forceinline__ float warp_rank16(float mx) {
    const int lane = threadIdx.x & 31;
    float sx = mx;
#pragma unroll
    for (int k = 2; k <= 32; k <<= 1) {
#pragma unroll
        for (int j = k >> 1; j > 0; j >>= 1) {
            float y = __shfl_xor_sync(FULL, sx, j);
            bool up      = ((lane & k) == 0);
            bool lower   = ((lane & j) == 0);
            bool wantMax = up ? !lower : lower;
            sx = wantMax ? fmaxf(sx, y) : fminf(sx, y);
        }
    }
    return __shfl_sync(FULL, sx, 16);
}

// ---- packed sort key: (d desc, idx asc) <=> key desc; idx = ~(u32)key ----
__device__ __forceinline__ unsigned long long knn_key(float d, int idx) {
    unsigned u = __float_as_uint(d);
    u = (u & 0x80000000u) ? ~u : (u | 0x80000000u);
    return ((unsigned long long)u << 32) | (unsigned)(~idx);
}

// descending bitonic sort of 64 keys; element e: r0=lane, r1=lane+32
__device__ __forceinline__ void bitonic64_desc(unsigned long long& r0,
                                               unsigned long long& r1) {
    const int lane = threadIdx.x & 31;
#pragma unroll
    for (int k = 2; k <= 16; k <<= 1) {
#pragma unroll
        for (int j = k >> 1; j > 0; j >>= 1) {
            bool segUp = ((lane & k) == 0);
            bool lower = ((lane & j) == 0);
            bool keepMax = (lower == segUp);
            unsigned long long o0 = __shfl_xor_sync(FULL, r0, j);
            unsigned long long o1 = __shfl_xor_sync(FULL, r1, j);
            r0 = keepMax ? (r0 > o0 ? r0 : o0) : (r0 > o0 ? o0 : r0);
            r1 = keepMax ? (r1 > o1 ? r1 : o1) : (r1 > o1 ? o1 : r1);
        }
    }
#pragma unroll
    for (int j = 16; j > 0; j >>= 1) {       // k=32: r1 opposite direction
        bool lower = ((lane & j) == 0);
        unsigned long long o0 = __shfl_xor_sync(FULL, r0, j);
        unsigned long long o1 = __shfl_xor_sync(FULL, r1, j);
        r0 = lower  ? (r0 > o0 ? r0 : o0) : (r0 > o0 ? o0 : r0);
        r1 = !lower ? (r1 > o1 ? r1 : o1) : (r1 > o1 ? o1 : r1);
    }
    {
        unsigned long long mx = r0 > r1 ? r0 : r1;
        unsigned long long mn = r0 > r1 ? r1 : r0;
        r0 = mx; r1 = mn;
    }
#pragma unroll
    for (int j = 16; j > 0; j >>= 1) {
        bool lower = ((lane & j) == 0);
        unsigned long long o0 = __shfl_xor_sync(FULL, r0, j);
        unsigned long long o1 = __shfl_xor_sync(FULL, r1, j);
        r0 = lower ? (r0 > o0 ? r0 : o0) : (r0 > o0 ? o0 : r0);
        r1 = lower ? (r1 > o1 ? r1 : o1) : (r1 > o1 ? o1 : r1);
    }
}

// ---------------- kNN: 4 q/warp, HALF-scan threshold + smem hit lists -----
// Pass 1 scans candidates [0, NN/2): rank16-of-lane-maxes(S) <= t16(S) <=
// t16(full) for any subset S, so the threshold stays valid (just looser:
// ~33 expected hits, CAP=64, overflow -> exact fallback).
__global__ __launch_bounds__(256) void knn_kernel() {
    __shared__ float sval[8][QW][CAP];
    __shared__ int   sidx[8][QW][CAP];
    __shared__ int   scnt[8][QW];

    const int wid  = threadIdx.x >> 5;
    const int lane = threadIdx.x & 31;
    const int qbase = (blockIdx.x * 8 + wid) * QW;
    const int b    = qbase >> 12;
    const float4* PPb = g_PP + (size_t)b * NN;
    const int qloc = qbase & 4095;

    const float4 qp0 = __ldg(&PPb[qloc + 0]);
    const float4 qp1 = __ldg(&PPb[qloc + 1]);
    const float4 qp2 = __ldg(&PPb[qloc + 2]);
    const float4 qp3 = __ldg(&PPb[qloc + 3]);

    // ---- pass 1: per-lane max over HALF the candidates ----
    float ma0 = NEGINF, ma1 = NEGINF, ma2 = NEGINF, ma3 = NEGINF;
    float mb0 = NEGINF, mb1 = NEGINF, mb2 = NEGINF, mb3 = NEGINF;
    for (int mi0 = 0; mi0 < NN / 2; mi0 += 64) {
        float4 ca = __ldg(&PPb[mi0 + lane]);
        float4 cb = __ldg(&PPb[mi0 + 32 + lane]);
        ma0 = fmaxf(ma0, knn_dist(qp0, ca));
        ma1 = fmaxf(ma1, knn_dist(qp1, ca));
        ma2 = fmaxf(ma2, knn_dist(qp2, ca));
        ma3 = fmaxf(ma3, knn_dist(qp3, ca));
        mb0 = fmaxf(mb0, knn_dist(qp0, cb));
        mb1 = fmaxf(mb1, knn_dist(qp1, cb));
        mb2 = fmaxf(mb2, knn_dist(qp2, cb));
        mb3 = fmaxf(mb3, knn_dist(qp3, cb));
    }
    const float L0 = warp_rank16(fmaxf(ma0, mb0));
    const float L1 = warp_rank16(fmaxf(ma1, mb1));
    const float L2 = warp_rank16(fmaxf(ma2, mb2));
    const float L3 = warp_rank16(fmaxf(ma3, mb3));

    // ---- pass 2: emit hits (d >= L) over FULL candidate set ----
    if (lane < QW) scnt[wid][lane] = 0;
    __syncwarp();
#pragma unroll 2
    for (int mi0 = 0; mi0 < NN; mi0 += 32) {
        int mi = mi0 + lane;
        float4 c4 = __ldg(&PPb[mi]);
        float d0 = knn_dist(qp0, c4);
        float d1 = knn_dist(qp1, c4);
        float d2 = knn_dist(qp2, c4);
        float d3 = knn_dist(qp3, c4);
        bool p0 = d0 >= L0, p1 = d1 >= L1, p2 = d2 >= L2, p3 = d3 >= L3;
        if (p0 | p1 | p2 | p3) {
            if (p0) { int s = atomicAdd(&scnt[wid][0], 1);
                      if (s < CAP) { sval[wid][0][s] = d0; sidx[wid][0][s] = mi; } }
            if (p1) { int s = atomicAdd(&scnt[wid][1], 1);
                      if (s < CAP) { sval[wid][1][s] = d1; sidx[wid][1][s] = mi; } }
            if (p2) { int s = atomicAdd(&scnt[wid][2], 1);
                      if (s < CAP) { sval[wid][2][s] = d2; sidx[wid][2][s] = mi; } }
            if (p3) { int s = atomicAdd(&scnt[wid][3], 1);
                      if (s < CAP) { sval[wid][3][s] = d3; sidx[wid][3][s] = mi; } }
        }
    }
    __syncwarp();

    // ---- selection: one bitonic sort per query over <=64 hits ----
#pragma unroll
    for (int j = 0; j < QW; j++) {
        int cnt = scnt[wid][j];
        if (cnt <= CAP) {
            unsigned long long r0 = (lane < cnt)
                ? knn_key(sval[wid][j][lane], sidx[wid][j][lane]) : 0ull;
            unsigned long long r1 = (lane + 32 < cnt)
                ? knn_key(sval[wid][j][lane + 32], sidx[wid][j][lane + 32]) : 0ull;
            bitonic64_desc(r0, r1);
            if (lane < KNN)
                g_idx[(size_t)(qbase + j) * KNN + lane] = (int)~(unsigned)r0;
        } else {
            const float4 qpj = (j == 0) ? qp0 : (j == 1) ? qp1 : (j == 2) ? qp2 : qp3;
            knn_exact(PPb, qpj, qbase + j);
        }
    }
}

// ---------------- fused: per-warp stages + block-cooperative GEMVs --------
// (identical to the benched R12 kernel: hs store/load retained)
#define HSTR 65
#define ASTR 321   // per-point A stride; A[c*5+h], 64*5=320 -> pad 321
__global__ __launch_bounds__(256, 4) void fused_kernel(
    const float* __restrict__ x,  const float* __restrict__ bp2,
    const float* __restrict__ bfc, float* __restrict__ out)
{
    __shared__ float hs   [8 * KNN * HSTR];   // 8320 fl; overlaid by PART later
    __shared__ float attns[8 * KNN * NH];
    __shared__ float As   [8 * ASTR];         // A[p][c][h] padded
    __shared__ float aggs [8 * 65];           // agg[p][c] padded
    float* PART = hs;                          // 8cs*8p*64j = 4096 fl

    const int wid  = threadIdx.x >> 5;
    const int lane = threadIdx.x & 31;
    const int p    = blockIdx.x * 8 + wid;
    const int b    = p >> 12;

    float* hsb = hs    + wid * KNN * HSTR;
    float* atb = attns + wid * KNN * NH;

    const int k    = lane >> 1;
    const int half = lane & 1;

    float4 qp = g_PP[p];

    int m = 0;
    float4 kl4 = make_float4(0.f, 0.f, 0.f, 0.f);
    float pdx = 0.f, pdy = 0.f, pdz = 0.f;
    if (half == 0) {
        m = g_idx[(size_t)p * KNN + k];
        float4 np = g_PP[(size_t)b * NN + m];
        pdx = qp.x - np.x; pdy = qp.y - np.y; pdz = qp.z - np.z;
        kl4 = ((const float4*)g_KL)[(size_t)b * NN + m];
    }
    int src0 = lane & ~1;
    pdx = __shfl_sync(FULL, pdx, src0);
    pdy = __shfl_sync(FULL, pdy, src0);
    pdz = __shfl_sync(FULL, pdz, src0);

    float4 qm4 = ((const float4*)g_QM)[p];
    float4 cb4 = *(const float4*)g_CB;

    float mp0 = 0.f, mp1 = 0.f, mp2 = 0.f, mp3 = 0.f;
#pragma unroll 8
    for (int i = 0; i < 32; i++) {
        int c = half * 32 + i;
        float4 pw = ((const float4*)g_PW1)[c];
        float hv = fmaf(pw.x, pdx, fmaf(pw.y, pdy, fmaf(pw.z, pdz, pw.w)));
        float rh = fmaxf(hv, 0.f);
        hsb[k * HSTR + c] = rh;
        float4 wm4 = ((const float4*)g_Wpm)[c];
        mp0 = fmaf(rh, wm4.x, mp0); mp1 = fmaf(rh, wm4.y, mp1);
        mp2 = fmaf(rh, wm4.z, mp2); mp3 = fmaf(rh, wm4.w, mp3);
    }
    mp0 += __shfl_xor_sync(FULL, mp0, 1);
    mp1 += __shfl_xor_sync(FULL, mp1, 1);
    mp2 += __shfl_xor_sync(FULL, mp2, 1);
    mp3 += __shfl_xor_sync(FULL, mp3, 1);

    float lg0 = qm4.x + cb4.x - kl4.x + mp0;
    float lg1 = qm4.y + cb4.y - kl4.y + mp1;
    float lg2 = qm4.z + cb4.z - kl4.z + mp2;
    float lg3 = qm4.w + cb4.w - kl4.w + mp3;
    float m0 = lg0, m1 = lg1, m2 = lg2, m3 = lg3;
#pragma unroll
    for (int off = 2; off < 32; off <<= 1) {
        m0 = fmaxf(m0, __shfl_xor_sync(FULL, m0, off));
        m1 = fmaxf(m1, __shfl_xor_sync(FULL, m1, off));
        m2 = fmaxf(m2, __shfl_xor_sync(FULL, m2, off));
        m3 = fmaxf(m3, __shfl_xor_sync(FULL, m3, off));
    }
    float e0 = __expf(lg0 - m0), e1 = __expf(lg1 - m1);
    float e2 = __expf(lg2 - m2), e3 = __expf(lg3 - m3);
    float s0 = e0, s1 = e1, s2 = e2, s3 = e3;
#pragma unroll
    for (int off = 2; off < 32; off <<= 1) {
        s0 += __shfl_xor_sync(FULL, s0, off);
        s1 += __shfl_xor_sync(FULL, s1, off);
        s2 += __shfl_xor_sync(FULL, s2, off);
        s3 += __shfl_xor_sync(FULL, s3, off);
    }
    if (half == 0)
        ((float4*)atb)[k] = make_float4(e0 / s0, e1 / s1, e2 / s2, e3 / s3);
    __syncwarp();

    // ---- S5: attn-weighted hidden (A) and V (av) ----
    float A0[4] = {0.f, 0.f, 0.f, 0.f};
    float A1[4] = {0.f, 0.f, 0.f, 0.f};
    float av0 = 0.f, av1 = 0.f;
    bool lo = (lane < 16);
#pragma unroll
    for (int kk = 0; kk < KNN; kk++) {
        float4 a4 = ((const float4*)atb)[kk];
        float hv0 = hsb[kk * HSTR + lane];
        float hv1 = hsb[kk * HSTR + lane + 32];
        A0[0] = fmaf(a4.x, hv0, A0[0]); A0[1] = fmaf(a4.y, hv0, A0[1]);
        A0[2] = fmaf(a4.z, hv0, A0[2]); A0[3] = fmaf(a4.w, hv0, A0[3]);
        A1[0] = fmaf(a4.x, hv1, A1[0]); A1[1] = fmaf(a4.y, hv1, A1[1]);
        A1[2] = fmaf(a4.z, hv1, A1[2]); A1[3] = fmaf(a4.w, hv1, A1[3]);
        int mk = __shfl_sync(FULL, m, kk * 2);
        const float* vr = g_V + ((size_t)b * NN + mk) * CC;
        float aw0 = lo ? a4.x : a4.y;
        float aw1 = lo ? a4.z : a4.w;
        av0 = fmaf(aw0, vr[lane],      av0);
        av1 = fmaf(aw1, vr[lane + 32], av1);
    }
#pragma unroll
    for (int h = 0; h < 4; h++) {
        As[wid * ASTR + lane * 5 + h]        = A0[h];
        As[wid * ASTR + (lane + 32) * 5 + h] = A1[h];
    }
    aggs[wid * 65 + lane]      = av0 + bp2[lane];
    aggs[wid * 65 + lane + 32] = av1 + bp2[lane + 32];
    __syncthreads();

    // ---- P1: pe-project, block-cooperative (4 points per thread) ----
    const int t  = threadIdx.x;
    const int jg = t & 15, jc = jg * 4;
    const int pg = (t >> 4) & 1;
    const int cs = t >> 5;
    const int hh = jg >> 2;
    {
        float4 ac[4];
#pragma unroll
        for (int pi = 0; pi < 4; pi++) ac[pi] = make_float4(0.f, 0.f, 0.f, 0.f);
#pragma unroll
        for (int ci = 0; ci < 8; ci++) {
            int c = cs * 8 + ci;
            float4 w = *(const float4*)&g_WpT[c * 64 + jc];
#pragma unroll
            for (int pi = 0; pi < 4; pi++) {
                float a = As[(pg * 4 + pi) * ASTR + c * 5 + hh];
                ac[pi].x = fmaf(w.x, a, ac[pi].x);
                ac[pi].y = fmaf(w.y, a, ac[pi].y);
                ac[pi].z = fmaf(w.z, a, ac[pi].z);
                ac[pi].w = fmaf(w.w, a, ac[pi].w);
            }
        }
#pragma unroll
        for (int pi = 0; pi < 4; pi++)
            *(float4*)&PART[(cs * 8 + pg * 4 + pi) * 64 + jc] = ac[pi];
    }
    __syncthreads();
    {   // reduce partials into aggs
        int pu = t >> 5, ju = t & 31;
        float r0 = 0.f, r1 = 0.f;
#pragma unroll
        for (int c8 = 0; c8 < 8; c8++) {
            float2 v = *(const float2*)&PART[(c8 * 8 + pu) * 64 + ju * 2];
            r0 += v.x; r1 += v.y;
        }
        aggs[pu * 65 + ju * 2]     += r0;
        aggs[pu * 65 + ju * 2 + 1] += r1;
    }
    __syncthreads();

    // ---- P2: fc, block-cooperative ----
    {
        float4 ac[4];
#pragma unroll
        for (int pi = 0; pi < 4; pi++) ac[pi] = make_float4(0.f, 0.f, 0.f, 0.f);
#pragma unroll
        for (int ci = 0; ci < 8; ci++) {
            int c = cs * 8 + ci;
            float4 w = *(const float4*)&g_WfcT[c * 64 + jc];
#pragma unroll
            for (int pi = 0; pi < 4; pi++) {
                float a = aggs[(pg * 4 + pi) * 65 + c];
                ac[pi].x = fmaf(w.x, a, ac[pi].x);
                ac[pi].y = fmaf(w.y, a, ac[pi].y);
                ac[pi].z = fmaf(w.z, a, ac[pi].z);
                ac[pi].w = fmaf(w.w, a, ac[pi].w);
            }
        }
        __syncthreads();   // all P2 reads of aggs done; PART safe to overwrite
#pragma unroll
        for (int pi = 0; pi < 4; pi++)
            *(float4*)&PART[(cs * 8 + pg * 4 + pi) * 64 + jc] = ac[pi];
    }
    __syncthreads();
    {   // final reduce + residual + output
        int pu = t >> 5, ju = t & 31;
        float r0 = 0.f, r1 = 0.f;
#pragma unroll
        for (int c8 = 0; c8 < 8; c8++) {
            float2 v = *(const float2*)&PART[(c8 * 8 + pu) * 64 + ju * 2];
            r0 += v.x; r1 += v.y;
        }
        size_t o = ((size_t)(blockIdx.x * 8 + pu)) * CC + ju * 2;
        float2 xv = *(const float2*)&x[o];
        float2 ov;
        ov.x = xv.x + bfc[ju * 2]     + r0;
        ov.y = xv.y + bfc[ju * 2 + 1] + r1;
        *(float2*)&out[o] = ov;
    }
}

// ---------------- launch ----------------
extern "C" void kernel_launch(void* const* d_in, const int* in_sizes, int n_in,
                              void* d_out, int out_size) {
    const float* x   = (const float*)d_in[0];
    const float* pos = (const float*)d_in[1];
    const float* Wq  = (const float*)d_in[2];
    const float* bq  = (const float*)d_in[3];
    const float* Wk  = (const float*)d_in[4];
    const float* bk  = (const float*)d_in[5];
    const float* Wv  = (const float*)d_in[6];
    const float* bv  = (const float*)d_in[7];
    const float* Wp1 = (const float*)d_in[8];
    const float* bp1 = (const float*)d_in[9];
    const float* Wp2 = (const float*)d_in[10];
    const float* bp2 = (const float*)d_in[11];
    const float* Wfc = (const float*)d_in[12];
    const float* bfc = (const float*)d_in[13];
    float* out = (float*)d_out;

    cudaFuncSetAttribute(fused_kernel,
                         cudaFuncAttributePreferredSharedMemoryCarveout, 100);

    prep1_kernel<<<16, 256>>>(Wq, bq, Wk, bk, Wv, Wp1, bp1, Wp2, bp2, Wfc);
    prep2_kernel<<<(BB * NN) / 16, 256>>>(x, pos, bv);
    knn_kernel<<<(BB * NN) / (8 * QW), 256>>>();
    fused_kernel<<<(BB * NN) / 8, 256>>>(x, bp2, bfc, out);
}

// round 16
// speedup vs baseline: 1.9195x; 1.9195x over previous
#include <cuda_runtime.h>
#include <math.h>

#define BB   4
#define NN   4096
#define CC   64
#define KNN  16
#define NH   4
#define QW   4
#define CAP  64
#define FULL 0xffffffffu
#define NEGINF (-3.402823466e+38f)

// ---------------- device scratch (allocation-free) ----------------
__device__ int    g_idx[BB * NN * KNN];
__device__ float4 g_PP [BB * NN];            // packed pos (x,y,z,|p|^2)
__device__ float  g_V  [BB * NN * CC];       // x @ Wv^T + bv
__device__ float  g_KL [BB * NN * NH];
__device__ float  g_QM [BB * NN * NH];
__device__ float  g_WvT [CC * CC];
__device__ float  g_WpT [CC * CC];
__device__ float  g_WfcT[CC * CC];
__device__ float  g_Wkm [CC * NH];
__device__ float  g_Wqm [CC * NH];
__device__ float  g_Wpm [CC * NH];
__device__ float  g_PW1 [CC * 4];
__device__ float  g_CB  [NH];

// ---------------- prep1 ----------------
__global__ void prep1_kernel(const float* __restrict__ Wq, const float* __restrict__ bq,
                             const float* __restrict__ Wk, const float* __restrict__ bk,
                             const float* __restrict__ Wv,
                             const float* __restrict__ Wp1, const float* __restrict__ bp1,
                             const float* __restrict__ Wp2, const float* __restrict__ bp2,
                             const float* __restrict__ Wfc) {
    int tg = blockIdx.x * 256 + threadIdx.x;
    {
        int r = tg >> 6, c = tg & 63;
        g_WvT [c * CC + r] = Wv [tg];
        g_WpT [c * CC + r] = Wp2[tg];
        g_WfcT[c * CC + r] = Wfc[tg];
    }
    if (blockIdx.x == 0) {
        int t = threadIdx.x;
        int c = t >> 2, h = t & 3;
        float sk = 0.f, sq = 0.f, sp = 0.f;
#pragma unroll
        for (int d = 0; d < 16; d++) {
            sk += Wk [(h * 16 + d) * CC + c];
            sq += Wq [(h * 16 + d) * CC + c];
            sp += Wp2[(h * 16 + d) * CC + c];
        }
        g_Wkm[c * NH + h] = sk * (1.f / 16.f);
        g_Wqm[c * NH + h] = sq * (1.f / 16.f);
        g_Wpm[c * NH + h] = sp * (1.f / 16.f);
        if (t < CC) {
            g_PW1[t * 4 + 0] = Wp1[t * 3 + 0];
            g_PW1[t * 4 + 1] = Wp1[t * 3 + 1];
            g_PW1[t * 4 + 2] = Wp1[t * 3 + 2];
            g_PW1[t * 4 + 3] = bp1[t];
        }
        if (t < NH) {
            float s1 = 0.f, s2 = 0.f, s3 = 0.f;
            for (int d = 0; d < 16; d++) {
                s1 += bq [t * 16 + d];
                s2 += bk [t * 16 + d];
                s3 += bp2[t * 16 + d];
            }
            g_CB[t] = (s1 - s2 + s3) * (1.f / 16.f);
        }
    }
}

// ---------------- prep2 ----------------
__global__ __launch_bounds__(256) void prep2_kernel(const float* __restrict__ x,
                                                    const float* __restrict__ pos,
                                                    const float* __restrict__ bv) {
    __shared__ float xs[16 * CC];
    const int t = threadIdx.x;
    const int pbase = blockIdx.x * 16;

    ((float4*)xs)[t] = ((const float4*)(x + (size_t)pbase * CC))[t];
    __syncthreads();

    const int pt = t >> 4;
    const int jj = t & 15;
    const int p  = pbase + pt;
    const float* xr = xs + pt * CC;

    float a0 = bv[jj * 4 + 0], a1 = bv[jj * 4 + 1],
          a2 = bv[jj * 4 + 2], a3 = bv[jj * 4 + 3];
#pragma unroll 8
    for (int c = 0; c < CC; c++) {
        float xv = xr[c];
        float4 w = ((const float4*)(g_WvT + c * CC))[jj];
        a0 = fmaf(xv, w.x, a0); a1 = fmaf(xv, w.y, a1);
        a2 = fmaf(xv, w.z, a2); a3 = fmaf(xv, w.w, a3);
    }
    ((float4*)(g_V + (size_t)p * CC))[jj] = make_float4(a0, a1, a2, a3);

    if (jj < 4) {
        float s = 0.f;
#pragma unroll 8
        for (int c = 0; c < CC; c++) s = fmaf(xr[c], g_Wkm[c * 4 + jj], s);
        g_KL[(size_t)p * 4 + jj] = s;
    } else if (jj < 8) {
        int h = jj - 4;
        float s = 0.f;
#pragma unroll 8
        for (int c = 0; c < CC; c++) s = fmaf(xr[c], g_Wqm[c * 4 + h], s);
        g_QM[(size_t)p * 4 + h] = s;
    } else if (jj == 8) {
        float px = pos[(size_t)p * 3 + 0];
        float py = pos[(size_t)p * 3 + 1];
        float pz = pos[(size_t)p * 3 + 2];
        float nn = px * px; nn = fmaf(py, py, nn); nn = fmaf(pz, pz, nn);
        g_PP[p] = make_float4(px, py, pz, nn);
    }
}

// ---------------- kNN helpers ----------------
__device__ __forceinline__ float knn_dist(const float4 qp, const float4 c4) {
    float inner = qp.x * c4.x;
    inner = fmaf(qp.y, c4.y, inner);
    inner = fmaf(qp.z, c4.z, inner);
    return fmaf(2.0f, inner, (-qp.w) - c4.w);
}

__device__ __forceinline__ void warp_min16(float tv, int ti,
                                           float& mv, int& mI, int& ml) {
    mv = tv; mI = ti; ml = threadIdx.x & 31;
#pragma unroll
    for (int off = 1; off < 16; off <<= 1) {
        float ov = __shfl_xor_sync(FULL, mv, off);
        int   oi = __shfl_xor_sync(FULL, mI, off);
        int   ol = __shfl_xor_sync(FULL, ml, off);
        if (ov < mv || (ov == mv && oi > mI)) { mv = ov; mI = oi; ml = ol; }
    }
    mv = __shfl_sync(FULL, mv, 0);
    mI = __shfl_sync(FULL, mI, 0);
    ml = __shfl_sync(FULL, ml, 0);
}

__device__ void knn_exact(const float4* PPb, const float4 qp, int q) {
    const int lane = threadIdx.x & 31;
    float tv = NEGINF; int ti = 0x7fffffff - lane;
    float wv = NEGINF; int wm = 0x7fffffff;
    for (int mi0 = 0; mi0 < NN; mi0 += 32) {
        int mi = mi0 + lane;
        float d = knn_dist(qp, PPb[mi]);
        bool pred = (d > wv) || (d == wv && mi < wm);
        unsigned mask = __ballot_sync(FULL, pred);
        while (mask) {
            int src = __ffs(mask) - 1; mask &= mask - 1;
            float dc = __shfl_sync(FULL, d, src);
            int   mc = __shfl_sync(FULL, mi, src);
            float mv; int mI, ml;
            warp_min16(tv, ti, mv, mI, ml);
            if (dc > mv || (dc == mv && mc < mI)) {
                if (lane == ml) { tv = dc; ti = mc; }
                warp_min16(tv, ti, mv, mI, ml);
            }
            wv = mv; wm = mI;
        }
    }
    if (lane < KNN) g_idx[(size_t)q * KNN + lane] = ti;
}

__device__ __forceinline__ float warp_rank16(float mx) {
    const int lane = threadIdx.x & 31;
    float sx = mx;
#pragma unroll
    for (int k = 2; k <= 32; k <<= 1) {
#pragma unroll
        for (int j = k >> 1; j > 0; j >>= 1) {
            float y = __shfl_xor_sync(FULL, sx, j);
            bool up      = ((lane & k) == 0);
            bool lower   = ((lane & j) == 0);
            bool wantMax = up ? !lower : lower;
            sx = wantMax ? fmaxf(sx, y) : fminf(sx, y);
        }
    }
    return __shfl_sync(FULL, sx, 16);
}

// ---- packed sort key: (d desc, idx asc) <=> key desc; idx = ~(u32)key ----
__device__ __forceinline__ unsigned long long knn_key(float d, int idx) {
    unsigned u = __float_as_uint(d);
    u = (u & 0x80000000u) ? ~u : (u | 0x80000000u);
    return ((unsigned long long)u << 32) | (unsigned)(~idx);
}

// descending bitonic sort of 64 keys; element e: r0=lane, r1=lane+32
__device__ __forceinline__ void bitonic64_desc(unsigned long long& r0,
                                               unsigned long long& r1) {
    const int lane = threadIdx.x & 31;
#pragma unroll
    for (int k = 2; k <= 16; k <<= 1) {
#pragma unroll
        for (int j = k >> 1; j > 0; j >>= 1) {
            bool segUp = ((lane & k) == 0);
            bool lower = ((lane & j) == 0);
            bool keepMax = (lower == segUp);
            unsigned long long o0 = __shfl_xor_sync(FULL, r0, j);
            unsigned long long o1 = __shfl_xor_sync(FULL, r1, j);
            r0 = keepMax ? (r0 > o0 ? r0 : o0) : (r0 > o0 ? o0 : r0);
            r1 = keepMax ? (r1 > o1 ? r1 : o1) : (r1 > o1 ? o1 : r1);
        }
    }
#pragma unroll
    for (int j = 16; j > 0; j >>= 1) {       // k=32: r1 opposite direction
        bool lower = ((lane & j) == 0);
        unsigned long long o0 = __shfl_xor_sync(FULL, r0, j);
        unsigned long long o1 = __shfl_xor_sync(FULL, r1, j);
        r0 = lower  ? (r0 > o0 ? r0 : o0) : (r0 > o0 ? o0 : r0);
        r1 = !lower ? (r1 > o1 ? r1 : o1) : (r1 > o1 ? o1 : r1);
    }
    {
        unsigned long long mx = r0 > r1 ? r0 : r1;
        unsigned long long mn = r0 > r1 ? r1 : r0;
        r0 = mx; r1 = mn;
    }
#pragma unroll
    for (int j = 16; j > 0; j >>= 1) {
        bool lower = ((lane & j) == 0);
        unsigned long long o0 = __shfl_xor_sync(FULL, r0, j);
        unsigned long long o1 = __shfl_xor_sync(FULL, r1, j);
        r0 = lower ? (r0 > o0 ? r0 : o0) : (r0 > o0 ? o0 : r0);
        r1 = lower ? (r1 > o1 ? r1 : o1) : (r1 > o1 ? o1 : r1);
    }
}

// ---------------- kNN: 4 q/warp, FULL-scan threshold + smem hit lists -----
// (half-scan reverted: R15 showed the looser threshold drives hits toward
//  CAP and triggers the expensive exact fallback at high rate)
__global__ __launch_bounds__(256) void knn_kernel() {
    __shared__ float sval[8][QW][CAP];
    __shared__ int   sidx[8][QW][CAP];
    __shared__ int   scnt[8][QW];

    const int wid  = threadIdx.x >> 5;
    const int lane = threadIdx.x & 31;
    const int qbase = (blockIdx.x * 8 + wid) * QW;
    const int b    = qbase >> 12;
    const float4* PPb = g_PP + (size_t)b * NN;
    const int qloc = qbase & 4095;

    const float4 qp0 = __ldg(&PPb[qloc + 0]);
    const float4 qp1 = __ldg(&PPb[qloc + 1]);
    const float4 qp2 = __ldg(&PPb[qloc + 2]);
    const float4 qp3 = __ldg(&PPb[qloc + 3]);

    // ---- pass 1: per-lane max over ALL candidates ----
    float ma0 = NEGINF, ma1 = NEGINF, ma2 = NEGINF, ma3 = NEGINF;
    float mb0 = NEGINF, mb1 = NEGINF, mb2 = NEGINF, mb3 = NEGINF;
    for (int mi0 = 0; mi0 < NN; mi0 += 64) {
        float4 ca = __ldg(&PPb[mi0 + lane]);
        float4 cb = __ldg(&PPb[mi0 + 32 + lane]);
        ma0 = fmaxf(ma0, knn_dist(qp0, ca));
        ma1 = fmaxf(ma1, knn_dist(qp1, ca));
        ma2 = fmaxf(ma2, knn_dist(qp2, ca));
        ma3 = fmaxf(ma3, knn_dist(qp3, ca));
        mb0 = fmaxf(mb0, knn_dist(qp0, cb));
        mb1 = fmaxf(mb1, knn_dist(qp1, cb));
        mb2 = fmaxf(mb2, knn_dist(qp2, cb));
        mb3 = fmaxf(mb3, knn_dist(qp3, cb));
    }
    const float L0 = warp_rank16(fmaxf(ma0, mb0));
    const float L1 = warp_rank16(fmaxf(ma1, mb1));
    const float L2 = warp_rank16(fmaxf(ma2, mb2));
    const float L3 = warp_rank16(fmaxf(ma3, mb3));

    // ---- pass 2: emit hits (d >= L) to smem lists ----
    if (lane < QW) scnt[wid][lane] = 0;
    __syncwarp();
#pragma unroll 2
    for (int mi0 = 0; mi0 < NN; mi0 += 32) {
        int mi = mi0 + lane;
        float4 c4 = __ldg(&PPb[mi]);
        float d0 = knn_dist(qp0, c4);
        float d1 = knn_dist(qp1, c4);
        float d2 = knn_dist(qp2, c4);
        float d3 = knn_dist(qp3, c4);
        bool p0 = d0 >= L0, p1 = d1 >= L1, p2 = d2 >= L2, p3 = d3 >= L3;
        if (p0 | p1 | p2 | p3) {
            if (p0) { int s = atomicAdd(&scnt[wid][0], 1);
                      if (s < CAP) { sval[wid][0][s] = d0; sidx[wid][0][s] = mi; } }
            if (p1) { int s = atomicAdd(&scnt[wid][1], 1);
                      if (s < CAP) { sval[wid][1][s] = d1; sidx[wid][1][s] = mi; } }
            if (p2) { int s = atomicAdd(&scnt[wid][2], 1);
                      if (s < CAP) { sval[wid][2][s] = d2; sidx[wid][2][s] = mi; } }
            if (p3) { int s = atomicAdd(&scnt[wid][3], 1);
                      if (s < CAP) { sval[wid][3][s] = d3; sidx[wid][3][s] = mi; } }
        }
    }
    __syncwarp();

    // ---- selection: one bitonic sort per query over <=64 hits ----
#pragma unroll
    for (int j = 0; j < QW; j++) {
        int cnt = scnt[wid][j];
        if (cnt <= CAP) {
            unsigned long long r0 = (lane < cnt)
                ? knn_key(sval[wid][j][lane], sidx[wid][j][lane]) : 0ull;
            unsigned long long r1 = (lane + 32 < cnt)
                ? knn_key(sval[wid][j][lane + 32], sidx[wid][j][lane + 32]) : 0ull;
            bitonic64_desc(r0, r1);
            if (lane < KNN)
                g_idx[(size_t)(qbase + j) * KNN + lane] = (int)~(unsigned)r0;
        } else {
            const float4 qpj = (j == 0) ? qp0 : (j == 1) ? qp1 : (j == 2) ? qp2 : qp3;
            knn_exact(PPb, qpj, qbase + j);
        }
    }
}

// ---------------- fused: recompute-h, block-cooperative GEMVs -------------
#define ASTR 321   // per-point A stride; A[c*5+h], 64*5=320 -> pad 321
__global__ __launch_bounds__(256, 4) void fused_kernel(
    const float* __restrict__ x,  const float* __restrict__ bp2,
    const float* __restrict__ bfc, float* __restrict__ out)
{
    __shared__ float scratch[4096];           // PART (P1/P2 partials)
    __shared__ float pds  [8 * KNN * 4];      // pos-diff float4 per (wid,k)
    __shared__ float attns[8 * KNN * NH];
    __shared__ float As   [8 * ASTR];         // A[p][c][h] padded
    __shared__ float aggs [8 * 65];           // agg[p][c] padded
    float* PART = scratch;

    const int wid  = threadIdx.x >> 5;
    const int lane = threadIdx.x & 31;
    const int p    = blockIdx.x * 8 + wid;
    const int b    = p >> 12;

    float* atb = attns + wid * KNN * NH;

    const int k    = lane >> 1;
    const int half = lane & 1;

    float4 qp = g_PP[p];

    // per-lane Wp1 rows for channels c=lane and c=lane+32 (used in S5)
    const float4 pwA = ((const float4*)g_PW1)[lane];
    const float4 pwB = ((const float4*)g_PW1)[lane + 32];

    int m = 0;
    float4 kl4 = make_float4(0.f, 0.f, 0.f, 0.f);
    float pdx = 0.f, pdy = 0.f, pdz = 0.f;
    if (half == 0) {
        m = g_idx[(size_t)p * KNN + k];
        float4 np = g_PP[(size_t)b * NN + m];
        pdx = qp.x - np.x; pdy = qp.y - np.y; pdz = qp.z - np.z;
        kl4 = ((const float4*)g_KL)[(size_t)b * NN + m];
        *(float4*)&pds[(wid * KNN + k) * 4] = make_float4(pdx, pdy, pdz, 0.f);
    }
    int src0 = lane & ~1;
    pdx = __shfl_sync(FULL, pdx, src0);
    pdy = __shfl_sync(FULL, pdy, src0);
    pdz = __shfl_sync(FULL, pdz, src0);

    float4 qm4 = ((const float4*)g_QM)[p];
    float4 cb4 = *(const float4*)g_CB;

    // head-mean pe (h recomputed inline; no hs store)
    float mp0 = 0.f, mp1 = 0.f, mp2 = 0.f, mp3 = 0.f;
#pragma unroll 8
    for (int i = 0; i < 32; i++) {
        int c = half * 32 + i;
        float4 pw = ((const float4*)g_PW1)[c];
        float hv = fmaf(pw.x, pdx, fmaf(pw.y, pdy, fmaf(pw.z, pdz, pw.w)));
        float rh = fmaxf(hv, 0.f);
        float4 wm4 = ((const float4*)g_Wpm)[c];
        mp0 = fmaf(rh, wm4.x, mp0); mp1 = fmaf(rh, wm4.y, mp1);
        mp2 = fmaf(rh, wm4.z, mp2); mp3 = fmaf(rh, wm4.w, mp3);
    }
    mp0 += __shfl_xor_sync(FULL, mp0, 1);
    mp1 += __shfl_xor_sync(FULL, mp1, 1);
    mp2 += __shfl_xor_sync(FULL, mp2, 1);
    mp3 += __shfl_xor_sync(FULL, mp3, 1);

    float lg0 = qm4.x + cb4.x - kl4.x + mp0;
    float lg1 = qm4.y + cb4.y - kl4.y + mp1;
    float lg2 = qm4.z + cb4.z - kl4.z + mp2;
    float lg3 = qm4.w + cb4.w - kl4.w + mp3;
    float m0 = lg0, m1 = lg1, m2 = lg2, m3 = lg3;
#pragma unroll
    for (int off = 2; off < 32; off <<= 1) {
        m0 = fmaxf(m0, __shfl_xor_sync(FULL, m0, off));
        m1 = fmaxf(m1, __shfl_xor_sync(FULL, m1, off));
        m2 = fmaxf(m2, __shfl_xor_sync(FULL, m2, off));
        m3 = fmaxf(m3, __shfl_xor_sync(FULL, m3, off));
    }
    float e0 = __expf(lg0 - m0), e1 = __expf(lg1 - m1);
    float e2 = __expf(lg2 - m2), e3 = __expf(lg3 - m3);
    float s0 = e0, s1 = e1, s2 = e2, s3 = e3;
#pragma unroll
    for (int off = 2; off < 32; off <<= 1) {
        s0 += __shfl_xor_sync(FULL, s0, off);
        s1 += __shfl_xor_sync(FULL, s1, off);
        s2 += __shfl_xor_sync(FULL, s2, off);
        s3 += __shfl_xor_sync(FULL, s3, off);
    }
    if (half == 0)
        ((float4*)atb)[k] = make_float4(e0 / s0, e1 / s1, e2 / s2, e3 / s3);
    __syncwarp();

    // ---- S5: attn-weighted hidden (A, recomputed) and V (av) ----
    float A0[4] = {0.f, 0.f, 0.f, 0.f};
    float A1[4] = {0.f, 0.f, 0.f, 0.f};
    float av0 = 0.f, av1 = 0.f;
    bool lo = (lane < 16);
#pragma unroll
    for (int kk = 0; kk < KNN; kk++) {
        float4 a4  = ((const float4*)atb)[kk];
        float4 pd4 = *(const float4*)&pds[(wid * KNN + kk) * 4];  // broadcast
        float hv0 = fmaxf(fmaf(pwA.x, pd4.x, fmaf(pwA.y, pd4.y,
                          fmaf(pwA.z, pd4.z, pwA.w))), 0.f);
        float hv1 = fmaxf(fmaf(pwB.x, pd4.x, fmaf(pwB.y, pd4.y,
                          fmaf(pwB.z, pd4.z, pwB.w))), 0.f);
        A0[0] = fmaf(a4.x, hv0, A0[0]); A0[1] = fmaf(a4.y, hv0, A0[1]);
        A0[2] = fmaf(a4.z, hv0, A0[2]); A0[3] = fmaf(a4.w, hv0, A0[3]);
        A1[0] = fmaf(a4.x, hv1, A1[0]); A1[1] = fmaf(a4.y, hv1, A1[1]);
        A1[2] = fmaf(a4.z, hv1, A1[2]); A1[3] = fmaf(a4.w, hv1, A1[3]);
        int mk = __shfl_sync(FULL, m, kk * 2);
        const float* vr = g_V + ((size_t)b * NN + mk) * CC;
        float aw0 = lo ? a4.x : a4.y;
        float aw1 = lo ? a4.z : a4.w;
        av0 = fmaf(aw0, vr[lane],      av0);
        av1 = fmaf(aw1, vr[lane + 32], av1);
    }
#pragma unroll
    for (int h = 0; h < 4; h++) {
        As[wid * ASTR + lane * 5 + h]        = A0[h];
        As[wid * ASTR + (lane + 32) * 5 + h] = A1[h];
    }
    aggs[wid * 65 + lane]      = av0 + bp2[lane];
    aggs[wid * 65 + lane + 32] = av1 + bp2[lane + 32];
    __syncthreads();

    // ---- P1: pe-project, block-cooperative (4 points per thread) ----
    const int t  = threadIdx.x;
    const int jg = t & 15, jc = jg * 4;
    const int pg = (t >> 4) & 1;
    const int cs = t >> 5;
    const int hh = jg >> 2;
    {
        float4 ac[4];
#pragma unroll
        for (int pi = 0; pi < 4; pi++) ac[pi] = make_float4(0.f, 0.f, 0.f, 0.f);
#pragma unroll
        for (int ci = 0; ci < 8; ci++) {
            int c = cs * 8 + ci;
            float4 w = *(const float4*)&g_WpT[c * 64 + jc];
#pragma unroll
            for (int pi = 0; pi < 4; pi++) {
                float a = As[(pg * 4 + pi) * ASTR + c * 5 + hh];
                ac[pi].x = fmaf(w.x, a, ac[pi].x);
                ac[pi].y = fmaf(w.y, a, ac[pi].y);
                ac[pi].z = fmaf(w.z, a, ac[pi].z);
                ac[pi].w = fmaf(w.w, a, ac[pi].w);
            }
        }
#pragma unroll
        for (int pi = 0; pi < 4; pi++)
            *(float4*)&PART[(cs * 8 + pg * 4 + pi) * 64 + jc] = ac[pi];
    }
    __syncthreads();
    {   // reduce partials into aggs
        int pu = t >> 5, ju = t & 31;
        float r0 = 0.f, r1 = 0.f;
#pragma unroll
        for (int c8 = 0; c8 < 8; c8++) {
            float2 v = *(const float2*)&PART[(c8 * 8 + pu) * 64 + ju * 2];
            r0 += v.x; r1 += v.y;
        }
        aggs[pu * 65 + ju * 2]     += r0;
        aggs[pu * 65 + ju * 2 + 1] += r1;
    }
    __syncthreads();

    // ---- P2: fc, block-cooperative ----
    {
        float4 ac[4];
#pragma unroll
        for (int pi = 0; pi < 4; pi++) ac[pi] = make_float4(0.f, 0.f, 0.f, 0.f);
#pragma unroll
        for (int ci = 0; ci < 8; ci++) {
            int c = cs * 8 + ci;
            float4 w = *(const float4*)&g_WfcT[c * 64 + jc];
#pragma unroll
            for (int pi = 0; pi < 4; pi++) {
                float a = aggs[(pg * 4 + pi) * 65 + c];
                ac[pi].x = fmaf(w.x, a, ac[pi].x);
                ac[pi].y = fmaf(w.y, a, ac[pi].y);
                ac[pi].z = fmaf(w.z, a, ac[pi].z);
                ac[pi].w = fmaf(w.w, a, ac[pi].w);
            }
        }
        __syncthreads();   // all P2 reads of aggs done; PART safe to overwrite
#pragma unroll
        for (int pi = 0; pi < 4; pi++)
            *(float4*)&PART[(cs * 8 + pg * 4 + pi) * 64 + jc] = ac[pi];
    }
    __syncthreads();
    {   // final reduce + residual + output
        int pu = t >> 5, ju = t & 31;
        float r0 = 0.f, r1 = 0.f;
#pragma unroll
        for (int c8 = 0; c8 < 8; c8++) {
            float2 v = *(const float2*)&PART[(c8 * 8 + pu) * 64 + ju * 2];
            r0 += v.x; r1 += v.y;
        }
        size_t o = ((size_t)(blockIdx.x * 8 + pu)) * CC + ju * 2;
        float2 xv = *(const float2*)&x[o];
        float2 ov;
        ov.x = xv.x + bfc[ju * 2]     + r0;
        ov.y = xv.y + bfc[ju * 2 + 1] + r1;
        *(float2*)&out[o] = ov;
    }
}

// ---------------- launch ----------------
extern "C" void kernel_launch(void* const* d_in, const int* in_sizes, int n_in,
                              void* d_out, int out_size) {
    const float* x   = (const float*)d_in[0];
    const float* pos = (const float*)d_in[1];
    const float* Wq  = (const float*)d_in[2];
    const float* bq  = (const float*)d_in[3];
    const float* Wk  = (const float*)d_in[4];
    const float* bk  = (const float*)d_in[5];
    const float* Wv  = (const float*)d_in[6];
    const float* bv  = (const float*)d_in[7];
    const float* Wp1 = (const float*)d_in[8];
    const float* bp1 = (const float*)d_in[9];
    const float* Wp2 = (const float*)d_in[10];
    const float* bp2 = (const float*)d_in[11];
    const float* Wfc = (const float*)d_in[12];
    const float* bfc = (const float*)d_in[13];
    float* out = (float*)d_out;

    cudaFuncSetAttribute(fused_kernel,
                         cudaFuncAttributePreferredSharedMemoryCarveout, 100);

    prep1_kernel<<<16, 256>>>(Wq, bq, Wk, bk, Wv, Wp1, bp1, Wp2, bp2, Wfc);
    prep2_kernel<<<(BB * NN) / 16, 256>>>(x, pos, bv);
    knn_kernel<<<(BB * NN) / (8 * QW), 256>>>();
    fused_kernel<<<(BB * NN) / 8, 256>>>(x, bp2, bfc, out);
}

// round 17
// speedup vs baseline: 2.0044x; 1.0442x over previous
#include <cuda_runtime.h>
#include <math.h>

#define BB   4
#define NN   4096
#define CC   64
#define KNN  16
#define NH   4
#define QW   4
#define CAP  64
#define FULL 0xffffffffu
#define NEGINF (-3.402823466e+38f)

// ---------------- device scratch (allocation-free) ----------------
__device__ int    g_idx[BB * NN * KNN];
__device__ float4 g_PP [BB * NN];            // packed pos (x,y,z,|p|^2)
__device__ float  g_V  [BB * NN * CC];       // x @ Wv^T + bv
__device__ float  g_KL [BB * NN * NH];
__device__ float  g_QM [BB * NN * NH];
__device__ float  g_WvT [CC * CC];
__device__ float  g_WpT [CC * CC];
__device__ float  g_WfcT[CC * CC];
__device__ float  g_Wkm [CC * NH];
__device__ float  g_Wqm [CC * NH];
__device__ float  g_Wpm [CC * NH];
__device__ float  g_PW1 [CC * 4];
__device__ float  g_CB  [NH];

// constant-port copies (uniform access only): populated via async D2D memcpy
__constant__ float4 c_PW1v[CC];
__constant__ float4 c_Wpmv[CC];
__constant__ float  c_CB[NH];

// ---------------- prep1 ----------------
__global__ void prep1_kernel(const float* __restrict__ Wq, const float* __restrict__ bq,
                             const float* __restrict__ Wk, const float* __restrict__ bk,
                             const float* __restrict__ Wv,
                             const float* __restrict__ Wp1, const float* __restrict__ bp1,
                             const float* __restrict__ Wp2, const float* __restrict__ bp2,
                             const float* __restrict__ Wfc) {
    int tg = blockIdx.x * 256 + threadIdx.x;
    {
        int r = tg >> 6, c = tg & 63;
        g_WvT [c * CC + r] = Wv [tg];
        g_WpT [c * CC + r] = Wp2[tg];
        g_WfcT[c * CC + r] = Wfc[tg];
    }
    if (blockIdx.x == 0) {
        int t = threadIdx.x;
        int c = t >> 2, h = t & 3;
        float sk = 0.f, sq = 0.f, sp = 0.f;
#pragma unroll
        for (int d = 0; d < 16; d++) {
            sk += Wk [(h * 16 + d) * CC + c];
            sq += Wq [(h * 16 + d) * CC + c];
            sp += Wp2[(h * 16 + d) * CC + c];
        }
        g_Wkm[c * NH + h] = sk * (1.f / 16.f);
        g_Wqm[c * NH + h] = sq * (1.f / 16.f);
        g_Wpm[c * NH + h] = sp * (1.f / 16.f);
        if (t < CC) {
            g_PW1[t * 4 + 0] = Wp1[t * 3 + 0];
            g_PW1[t * 4 + 1] = Wp1[t * 3 + 1];
            g_PW1[t * 4 + 2] = Wp1[t * 3 + 2];
            g_PW1[t * 4 + 3] = bp1[t];
        }
        if (t < NH) {
            float s1 = 0.f, s2 = 0.f, s3 = 0.f;
            for (int d = 0; d < 16; d++) {
                s1 += bq [t * 16 + d];
                s2 += bk [t * 16 + d];
                s3 += bp2[t * 16 + d];
            }
            g_CB[t] = (s1 - s2 + s3) * (1.f / 16.f);
        }
    }
}

// ---------------- prep2 ----------------
__global__ __launch_bounds__(256) void prep2_kernel(const float* __restrict__ x,
                                                    const float* __restrict__ pos,
                                                    const float* __restrict__ bv) {
    __shared__ float xs[16 * CC];
    const int t = threadIdx.x;
    const int pbase = blockIdx.x * 16;

    ((float4*)xs)[t] = ((const float4*)(x + (size_t)pbase * CC))[t];
    __syncthreads();

    const int pt = t >> 4;
    const int jj = t & 15;
    const int p  = pbase + pt;
    const float* xr = xs + pt * CC;

    float a0 = bv[jj * 4 + 0], a1 = bv[jj * 4 + 1],
          a2 = bv[jj * 4 + 2], a3 = bv[jj * 4 + 3];
#pragma unroll 8
    for (int c = 0; c < CC; c++) {
        float xv = xr[c];
        float4 w = ((const float4*)(g_WvT + c * CC))[jj];
        a0 = fmaf(xv, w.x, a0); a1 = fmaf(xv, w.y, a1);
        a2 = fmaf(xv, w.z, a2); a3 = fmaf(xv, w.w, a3);
    }
    ((float4*)(g_V + (size_t)p * CC))[jj] = make_float4(a0, a1, a2, a3);

    if (jj < 4) {
        float s = 0.f;
#pragma unroll 8
        for (int c = 0; c < CC; c++) s = fmaf(xr[c], g_Wkm[c * 4 + jj], s);
        g_KL[(size_t)p * 4 + jj] = s;
    } else if (jj < 8) {
        int h = jj - 4;
        float s = 0.f;
#pragma unroll 8
        for (int c = 0; c < CC; c++) s = fmaf(xr[c], g_Wqm[c * 4 + h], s);
        g_QM[(size_t)p * 4 + h] = s;
    } else if (jj == 8) {
        float px = pos[(size_t)p * 3 + 0];
        float py = pos[(size_t)p * 3 + 1];
        float pz = pos[(size_t)p * 3 + 2];
        float nn = px * px; nn = fmaf(py, py, nn); nn = fmaf(pz, pz, nn);
        g_PP[p] = make_float4(px, py, pz, nn);
    }
}

// ---------------- kNN helpers ----------------
__device__ __forceinline__ float knn_dist(const float4 qp, const float4 c4) {
    float inner = qp.x * c4.x;
    inner = fmaf(qp.y, c4.y, inner);
    inner = fmaf(qp.z, c4.z, inner);
    return fmaf(2.0f, inner, (-qp.w) - c4.w);
}

__device__ __forceinline__ void warp_min16(float tv, int ti,
                                           float& mv, int& mI, int& ml) {
    mv = tv; mI = ti; ml = threadIdx.x & 31;
#pragma unroll
    for (int off = 1; off < 16; off <<= 1) {
        float ov = __shfl_xor_sync(FULL, mv, off);
        int   oi = __shfl_xor_sync(FULL, mI, off);
        int   ol = __shfl_xor_sync(FULL, ml, off);
        if (ov < mv || (ov == mv && oi > mI)) { mv = ov; mI = oi; ml = ol; }
    }
    mv = __shfl_sync(FULL, mv, 0);
    mI = __shfl_sync(FULL, mI, 0);
    ml = __shfl_sync(FULL, ml, 0);
}

__device__ void knn_exact(const float4* PPb, const float4 qp, int q) {
    const int lane = threadIdx.x & 31;
    float tv = NEGINF; int ti = 0x7fffffff - lane;
    float wv = NEGINF; int wm = 0x7fffffff;
    for (int mi0 = 0; mi0 < NN; mi0 += 32) {
        int mi = mi0 + lane;
        float d = knn_dist(qp, PPb[mi]);
        bool pred = (d > wv) || (d == wv && mi < wm);
        unsigned mask = __ballot_sync(FULL, pred);
        while (mask) {
            int src = __ffs(mask) - 1; mask &= mask - 1;
            float dc = __shfl_sync(FULL, d, src);
            int   mc = __shfl_sync(FULL, mi, src);
            float mv; int mI, ml;
            warp_min16(tv, ti, mv, mI, ml);
            if (dc > mv || (dc == mv && mc < mI)) {
                if (lane == ml) { tv = dc; ti = mc; }
                warp_min16(tv, ti, mv, mI, ml);
            }
            wv = mv; wm = mI;
        }
    }
    if (lane < KNN) g_idx[(size_t)q * KNN + lane] = ti;
}

__device__ __forceinline__ float warp_rank16(float mx) {
    const int lane = threadIdx.x & 31;
    float sx = mx;
#pragma unroll
    for (int k = 2; k <= 32; k <<= 1) {
#pragma unroll
        for (int j = k >> 1; j > 0; j >>= 1) {
            float y = __shfl_xor_sync(FULL, sx, j);
            bool up      = ((lane & k) == 0);
            bool lower   = ((lane & j) == 0);
            bool wantMax = up ? !lower : lower;
            sx = wantMax ? fmaxf(sx, y) : fminf(sx, y);
        }
    }
    return __shfl_sync(FULL, sx, 16);
}

// ---- packed sort key: (d desc, idx asc) <=> key desc; idx = ~(u32)key ----
__device__ __forceinline__ unsigned long long knn_key(float d, int idx) {
    unsigned u = __float_as_uint(d);
    u = (u & 0x80000000u) ? ~u : (u | 0x80000000u);
    return ((unsigned long long)u << 32) | (unsigned)(~idx);
}

// descending bitonic sort of 64 keys; element e: r0=lane, r1=lane+32
__device__ __forceinline__ void bitonic64_desc(unsigned long long& r0,
                                               unsigned long long& r1) {
    const int lane = threadIdx.x & 31;
#pragma unroll
    for (int k = 2; k <= 16; k <<= 1) {
#pragma unroll
        for (int j = k >> 1; j > 0; j >>= 1) {
            bool segUp = ((lane & k) == 0);
            bool lower = ((lane & j) == 0);
            bool keepMax = (lower == segUp);
            unsigned long long o0 = __shfl_xor_sync(FULL, r0, j);
            unsigned long long o1 = __shfl_xor_sync(FULL, r1, j);
            r0 = keepMax ? (r0 > o0 ? r0 : o0) : (r0 > o0 ? o0 : r0);
            r1 = keepMax ? (r1 > o1 ? r1 : o1) : (r1 > o1 ? o1 : r1);
        }
    }
#pragma unroll
    for (int j = 16; j > 0; j >>= 1) {       // k=32: r1 opposite direction
        bool lower = ((lane & j) == 0);
        unsigned long long o0 = __shfl_xor_sync(FULL, r0, j);
        unsigned long long o1 = __shfl_xor_sync(FULL, r1, j);
        r0 = lower  ? (r0 > o0 ? r0 : o0) : (r0 > o0 ? o0 : r0);
        r1 = !lower ? (r1 > o1 ? r1 : o1) : (r1 > o1 ? o1 : r1);
    }
    {
        unsigned long long mx = r0 > r1 ? r0 : r1;
        unsigned long long mn = r0 > r1 ? r1 : r0;
        r0 = mx; r1 = mn;
    }
#pragma unroll
    for (int j = 16; j > 0; j >>= 1) {
        bool lower = ((lane & j) == 0);
        unsigned long long o0 = __shfl_xor_sync(FULL, r0, j);
        unsigned long long o1 = __shfl_xor_sync(FULL, r1, j);
        r0 = lower ? (r0 > o0 ? r0 : o0) : (r0 > o0 ? o0 : r0);
        r1 = lower ? (r1 > o1 ? r1 : o1) : (r1 > o1 ? o1 : r1);
    }
}

// ---------------- kNN: 4 q/warp, FULL-scan threshold + smem hit lists -----
__global__ __launch_bounds__(256) void knn_kernel() {
    __shared__ float sval[8][QW][CAP];
    __shared__ int   sidx[8][QW][CAP];
    __shared__ int   scnt[8][QW];

    const int wid  = threadIdx.x >> 5;
    const int lane = threadIdx.x & 31;
    const int qbase = (blockIdx.x * 8 + wid) * QW;
    const int b    = qbase >> 12;
    const float4* PPb = g_PP + (size_t)b * NN;
    const int qloc = qbase & 4095;

    const float4 qp0 = __ldg(&PPb[qloc + 0]);
    const float4 qp1 = __ldg(&PPb[qloc + 1]);
    const float4 qp2 = __ldg(&PPb[qloc + 2]);
    const float4 qp3 = __ldg(&PPb[qloc + 3]);

    // ---- pass 1: per-lane max over ALL candidates ----
    float ma0 = NEGINF, ma1 = NEGINF, ma2 = NEGINF, ma3 = NEGINF;
    float mb0 = NEGINF, mb1 = NEGINF, mb2 = NEGINF, mb3 = NEGINF;
    for (int mi0 = 0; mi0 < NN; mi0 += 64) {
        float4 ca = __ldg(&PPb[mi0 + lane]);
        float4 cb = __ldg(&PPb[mi0 + 32 + lane]);
        ma0 = fmaxf(ma0, knn_dist(qp0, ca));
        ma1 = fmaxf(ma1, knn_dist(qp1, ca));
        ma2 = fmaxf(ma2, knn_dist(qp2, ca));
        ma3 = fmaxf(ma3, knn_dist(qp3, ca));
        mb0 = fmaxf(mb0, knn_dist(qp0, cb));
        mb1 = fmaxf(mb1, knn_dist(qp1, cb));
        mb2 = fmaxf(mb2, knn_dist(qp2, cb));
        mb3 = fmaxf(mb3, knn_dist(qp3, cb));
    }
    const float L0 = warp_rank16(fmaxf(ma0, mb0));
    const float L1 = warp_rank16(fmaxf(ma1, mb1));
    const float L2 = warp_rank16(fmaxf(ma2, mb2));
    const float L3 = warp_rank16(fmaxf(ma3, mb3));

    // ---- pass 2: emit hits (d >= L) to smem lists ----
    if (lane < QW) scnt[wid][lane] = 0;
    __syncwarp();
#pragma unroll 2
    for (int mi0 = 0; mi0 < NN; mi0 += 32) {
        int mi = mi0 + lane;
        float4 c4 = __ldg(&PPb[mi]);
        float d0 = knn_dist(qp0, c4);
        float d1 = knn_dist(qp1, c4);
        float d2 = knn_dist(qp2, c4);
        float d3 = knn_dist(qp3, c4);
        bool p0 = d0 >= L0, p1 = d1 >= L1, p2 = d2 >= L2, p3 = d3 >= L3;
        if (p0 | p1 | p2 | p3) {
            if (p0) { int s = atomicAdd(&scnt[wid][0], 1);
                      if (s < CAP) { sval[wid][0][s] = d0; sidx[wid][0][s] = mi; } }
            if (p1) { int s = atomicAdd(&scnt[wid][1], 1);
                      if (s < CAP) { sval[wid][1][s] = d1; sidx[wid][1][s] = mi; } }
            if (p2) { int s = atomicAdd(&scnt[wid][2], 1);
                      if (s < CAP) { sval[wid][2][s] = d2; sidx[wid][2][s] = mi; } }
            if (p3) { int s = atomicAdd(&scnt[wid][3], 1);
                      if (s < CAP) { sval[wid][3][s] = d3; sidx[wid][3][s] = mi; } }
        }
    }
    __syncwarp();

    // ---- selection: one bitonic sort per query over <=64 hits ----
#pragma unroll
    for (int j = 0; j < QW; j++) {
        int cnt = scnt[wid][j];
        if (cnt <= CAP) {
            unsigned long long r0 = (lane < cnt)
                ? knn_key(sval[wid][j][lane], sidx[wid][j][lane]) : 0ull;
            unsigned long long r1 = (lane + 32 < cnt)
                ? knn_key(sval[wid][j][lane + 32], sidx[wid][j][lane + 32]) : 0ull;
            bitonic64_desc(r0, r1);
            if (lane < KNN)
                g_idx[(size_t)(qbase + j) * KNN + lane] = (int)~(unsigned)r0;
        } else {
            const float4 qpj = (j == 0) ? qp0 : (j == 1) ? qp1 : (j == 2) ? qp2 : qp3;
            knn_exact(PPb, qpj, qbase + j);
        }
    }
}

// ---------------- fused: const-port mp-loop, recompute-h, coop GEMVs ------
#define ASTR 321
__global__ __launch_bounds__(256, 4) void fused_kernel(
    const float* __restrict__ x,  const float* __restrict__ bp2,
    const float* __restrict__ bfc, float* __restrict__ out)
{
    __shared__ float scratch[4096];           // PART (P1/P2 partials)
    __shared__ float pds  [8 * KNN * 4];      // pos-diff float4 per (wid,k)
    __shared__ float attns[8 * KNN * NH];
    __shared__ float As   [8 * ASTR];
    __shared__ float aggs [8 * 65];
    float* PART = scratch;

    const int wid  = threadIdx.x >> 5;
    const int lane = threadIdx.x & 31;
    const int p    = blockIdx.x * 8 + wid;
    const int b    = p >> 12;

    float* atb = attns + wid * KNN * NH;

    const int k    = lane >> 1;
    const int half = lane & 1;

    float4 qp = g_PP[p];

    // per-lane Wp1 rows (S5 recompute); constant-port uniform reads
    const float4 pwA = c_PW1v[lane];
    const float4 pwB = c_PW1v[lane + 32];

    int m = 0;
    float4 kl4 = make_float4(0.f, 0.f, 0.f, 0.f);
    float pdx = 0.f, pdy = 0.f, pdz = 0.f;
    if (half == 0) {
        m = g_idx[(size_t)p * KNN + k];
        float4 np = g_PP[(size_t)b * NN + m];
        pdx = qp.x - np.x; pdy = qp.y - np.y; pdz = qp.z - np.z;
        kl4 = ((const float4*)g_KL)[(size_t)b * NN + m];
        *(float4*)&pds[(wid * KNN + k) * 4] = make_float4(pdx, pdy, pdz, 0.f);
    }
    int src0 = lane & ~1;
    pdx = __shfl_sync(FULL, pdx, src0);
    pdy = __shfl_sync(FULL, pdy, src0);
    pdz = __shfl_sync(FULL, pdz, src0);

    float4 qm4 = ((const float4*)g_QM)[p];
    float4 cb4 = *(const float4*)c_CB;

    // head-mean pe: uniform-c loop over constant port (no L1 traffic,
    // full sum per lane -> no pair reduction needed)
    float mp0 = 0.f, mp1 = 0.f, mp2 = 0.f, mp3 = 0.f;
#pragma unroll 8
    for (int c = 0; c < CC; c++) {
        float4 pw = c_PW1v[c];
        float hv = fmaf(pw.x, pdx, fmaf(pw.y, pdy, fmaf(pw.z, pdz, pw.w)));
        float rh = fmaxf(hv, 0.f);
        float4 wm4 = c_Wpmv[c];
        mp0 = fmaf(rh, wm4.x, mp0); mp1 = fmaf(rh, wm4.y, mp1);
        mp2 = fmaf(rh, wm4.z, mp2); mp3 = fmaf(rh, wm4.w, mp3);
    }

    float lg0 = qm4.x + cb4.x - kl4.x + mp0;
    float lg1 = qm4.y + cb4.y - kl4.y + mp1;
    float lg2 = qm4.z + cb4.z - kl4.z + mp2;
    float lg3 = qm4.w + cb4.w - kl4.w + mp3;
    float m0 = lg0, m1 = lg1, m2 = lg2, m3 = lg3;
#pragma unroll
    for (int off = 2; off < 32; off <<= 1) {
        m0 = fmaxf(m0, __shfl_xor_sync(FULL, m0, off));
        m1 = fmaxf(m1, __shfl_xor_sync(FULL, m1, off));
        m2 = fmaxf(m2, __shfl_xor_sync(FULL, m2, off));
        m3 = fmaxf(m3, __shfl_xor_sync(FULL, m3, off));
    }
    float e0 = __expf(lg0 - m0), e1 = __expf(lg1 - m1);
    float e2 = __expf(lg2 - m2), e3 = __expf(lg3 - m3);
    float s0 = e0, s1 = e1, s2 = e2, s3 = e3;
#pragma unroll
    for (int off = 2; off < 32; off <<= 1) {
        s0 += __shfl_xor_sync(FULL, s0, off);
        s1 += __shfl_xor_sync(FULL, s1, off);
        s2 += __shfl_xor_sync(FULL, s2, off);
        s3 += __shfl_xor_sync(FULL, s3, off);
    }
    if (half == 0)
        ((float4*)atb)[k] = make_float4(e0 / s0, e1 / s1, e2 / s2, e3 / s3);
    __syncwarp();

    // ---- S5: attn-weighted hidden (A, recomputed) and V (av) ----
    float A0[4] = {0.f, 0.f, 0.f, 0.f};
    float A1[4] = {0.f, 0.f, 0.f, 0.f};
    float av0 = 0.f, av1 = 0.f;
    bool lo = (lane < 16);
#pragma unroll
    for (int kk = 0; kk < KNN; kk++) {
        float4 a4  = ((const float4*)atb)[kk];
        float4 pd4 = *(const float4*)&pds[(wid * KNN + kk) * 4];
        float hv0 = fmaxf(fmaf(pwA.x, pd4.x, fmaf(pwA.y, pd4.y,
                          fmaf(pwA.z, pd4.z, pwA.w))), 0.f);
        float hv1 = fmaxf(fmaf(pwB.x, pd4.x, fmaf(pwB.y, pd4.y,
                          fmaf(pwB.z, pd4.z, pwB.w))), 0.f);
        A0[0] = fmaf(a4.x, hv0, A0[0]); A0[1] = fmaf(a4.y, hv0, A0[1]);
        A0[2] = fmaf(a4.z, hv0, A0[2]); A0[3] = fmaf(a4.w, hv0, A0[3]);
        A1[0] = fmaf(a4.x, hv1, A1[0]); A1[1] = fmaf(a4.y, hv1, A1[1]);
        A1[2] = fmaf(a4.z, hv1, A1[2]); A1[3] = fmaf(a4.w, hv1, A1[3]);
        int mk = __shfl_sync(FULL, m, kk * 2);
        const float* vr = g_V + ((size_t)b * NN + mk) * CC;
        float aw0 = lo ? a4.x : a4.y;
        float aw1 = lo ? a4.z : a4.w;
        av0 = fmaf(aw0, vr[lane],      av0);
        av1 = fmaf(aw1, vr[lane + 32], av1);
    }
#pragma unroll
    for (int h = 0; h < 4; h++) {
        As[wid * ASTR + lane * 5 + h]        = A0[h];
        As[wid * ASTR + (lane + 32) * 5 + h] = A1[h];
    }
    aggs[wid * 65 + lane]      = av0 + bp2[lane];
    aggs[wid * 65 + lane + 32] = av1 + bp2[lane + 32];
    __syncthreads();

    // ---- P1: pe-project, block-cooperative ----
    const int t  = threadIdx.x;
    const int jg = t & 15, jc = jg * 4;
    const int pg = (t >> 4) & 1;
    const int cs = t >> 5;
    const int hh = jg >> 2;
    {
        float4 ac[4];
#pragma unroll
        for (int pi = 0; pi < 4; pi++) ac[pi] = make_float4(0.f, 0.f, 0.f, 0.f);
#pragma unroll
        for (int ci = 0; ci < 8; ci++) {
            int c = cs * 8 + ci;
            float4 w = *(const float4*)&g_WpT[c * 64 + jc];
#pragma unroll
            for (int pi = 0; pi < 4; pi++) {
                float a = As[(pg * 4 + pi) * ASTR + c * 5 + hh];
                ac[pi].x = fmaf(w.x, a, ac[pi].x);
                ac[pi].y = fmaf(w.y, a, ac[pi].y);
                ac[pi].z = fmaf(w.z, a, ac[pi].z);
                ac[pi].w = fmaf(w.w, a, ac[pi].w);
            }
        }
#pragma unroll
        for (int pi = 0; pi < 4; pi++)
            *(float4*)&PART[(cs * 8 + pg * 4 + pi) * 64 + jc] = ac[pi];
    }
    __syncthreads();
    {
        int pu = t >> 5, ju = t & 31;
        float r0 = 0.f, r1 = 0.f;
#pragma unroll
        for (int c8 = 0; c8 < 8; c8++) {
            float2 v = *(const float2*)&PART[(c8 * 8 + pu) * 64 + ju * 2];
            r0 += v.x; r1 += v.y;
        }
        aggs[pu * 65 + ju * 2]     += r0;
        aggs[pu * 65 + ju * 2 + 1] += r1;
    }
    __syncthreads();

    // ---- P2: fc, block-cooperative ----
    {
        float4 ac[4];
#pragma unroll
        for (int pi = 0; pi < 4; pi++) ac[pi] = make_float4(0.f, 0.f, 0.f, 0.f);
#pragma unroll
        for (int ci = 0; ci < 8; ci++) {
            int c = cs * 8 + ci;
            float4 w = *(const float4*)&g_WfcT[c * 64 + jc];
#pragma unroll
            for (int pi = 0; pi < 4; pi++) {
                float a = aggs[(pg * 4 + pi) * 65 + c];
                ac[pi].x = fmaf(w.x, a, ac[pi].x);
                ac[pi].y = fmaf(w.y, a, ac[pi].y);
                ac[pi].z = fmaf(w.z, a, ac[pi].z);
                ac[pi].w = fmaf(w.w, a, ac[pi].w);
            }
        }
        __syncthreads();
#pragma unroll
        for (int pi = 0; pi < 4; pi++)
            *(float4*)&PART[(cs * 8 + pg * 4 + pi) * 64 + jc] = ac[pi];
    }
    __syncthreads();
    {
        int pu = t >> 5, ju = t & 31;
        float r0 = 0.f, r1 = 0.f;
#pragma unroll
        for (int c8 = 0; c8 < 8; c8++) {
            float2 v = *(const float2*)&PART[(c8 * 8 + pu) * 64 + ju * 2];
            r0 += v.x; r1 += v.y;
        }
        size_t o = ((size_t)(blockIdx.x * 8 + pu)) * CC + ju * 2;
        float2 xv = *(const float2*)&x[o];
        float2 ov;
        ov.x = xv.x + bfc[ju * 2]     + r0;
        ov.y = xv.y + bfc[ju * 2 + 1] + r1;
        *(float2*)&out[o] = ov;
    }
}

// ---------------- launch ----------------
extern "C" void kernel_launch(void* const* d_in, const int* in_sizes, int n_in,
                              void* d_out, int out_size) {
    const float* x   = (const float*)d_in[0];
    const float* pos = (const float*)d_in[1];
    const float* Wq  = (const float*)d_in[2];
    const float* bq  = (const float*)d_in[3];
    const float* Wk  = (const float*)d_in[4];
    const float* bk  = (const float*)d_in[5];
    const float* Wv  = (const float*)d_in[6];
    const float* bv  = (const float*)d_in[7];
    const float* Wp1 = (const float*)d_in[8];
    const float* bp1 = (const float*)d_in[9];
    const float* Wp2 = (const float*)d_in[10];
    const float* bp2 = (const float*)d_in[11];
    const float* Wfc = (const float*)d_in[12];
    const float* bfc = (const float*)d_in[13];
    float* out = (float*)d_out;

    cudaFuncSetAttribute(fused_kernel,
                         cudaFuncAttributePreferredSharedMemoryCarveout, 100);

    prep1_kernel<<<16, 256>>>(Wq, bq, Wk, bk, Wv, Wp1, bp1, Wp2, bp2, Wfc);

    // async device-to-device copies into the constant bank (capturable
    // memcpy nodes; no allocation; ordered after prep1 on the same stream)
    void* pw1_ptr = nullptr; void* wpm_ptr = nullptr; void* cb_ptr = nullptr;
    cudaGetSymbolAddress(&pw1_ptr, g_PW1);
    cudaGetSymbolAddress(&wpm_ptr, g_Wpm);
    cudaGetSymbolAddress(&cb_ptr,  g_CB);
    cudaMemcpyToSymbolAsync(c_PW1v, pw1_ptr, CC * 4 * sizeof(float), 0,
                            cudaMemcpyDeviceToDevice, 0);
    cudaMemcpyToSymbolAsync(c_Wpmv, wpm_ptr, CC * 4 * sizeof(float), 0,
                            cudaMemcpyDeviceToDevice, 0);
    cudaMemcpyToSymbolAsync(c_CB,   cb_ptr,  NH * sizeof(float), 0,
                            cudaMemcpyDeviceToDevice, 0);

    prep2_kernel<<<(BB * NN) / 16, 256>>>(x, pos, bv);
    knn_kernel<<<(BB * NN) / (8 * QW), 256>>>();
    fused_kernel<<<(BB * NN) / 8, 256>>>(x, bp2, bfc, out);
}